// round 9
// baseline (speedup 1.0000x reference)
#include <cuda_runtime.h>
#include <cuda_bf16.h>

// Fused image preprocessing for [16,1280,960,3] fp32 -> [16,3,640,640] fp32:
// cast+rescale(1/255), bilinear resize (half-pixel centers, no antialias),
// normalize by mean/std, NHWC->NCHW transpose. All folded into one pass.
//
// Math structure exploited:
//  * vertical scale == 2.0 exactly: src_y frac is always 0.5, so each output
//    row is the mean of input rows (2y, 2y+1); the 0.5 folds into the
//    normalize scale, so staging is a plain add.
//  * horizontal scale == 1.5: output px group {4t..4t+3} reads input cols
//    {6t..6t+5} with fracs {.25,.75,.25,.75}; no clamping needed.
//
// Schedule: 1280 blocks x 240 threads, each block walks 8 rows (stride 1280).
// Software pipeline per iteration:
//   (1) prefetch next row-pair (6x LDG.128 -> registers)  [read stream armed]
//   (2) compute current row from smem buffer k; 160 threads emit one float4
//       __stcs per channel plane (coalesced STG.128)
//   (3) sum the prefetched pair, STS into buffer k^1
//   (4) single __syncthreads
// Two 11.52KB buffers = 23KB smem -> 8 blocks/SM, ~94% theoretical occupancy.

#define IN_H    1280
#define IN_W    960
#define OUT_HW  640
#define ROW_F   (IN_W * 3)       // 2880 floats per input row
#define ROW_F4  (ROW_F / 4)      // 720 float4
#define NT      240
#define PLANE   (OUT_HW * OUT_HW)
#define NROWS   (OUT_HW * 16)    // 10240 output rows
#define NBLK    1280             // 8 rows per block exactly
#define ITERS   (NROWS / NBLK)   // 8

__global__ __launch_bounds__(NT) void preproc_pipe_kernel(
    const float* __restrict__ img,   // [16, 1280, 960, 3]
    const float* __restrict__ mean,  // [3]
    const float* __restrict__ stdv,  // [3]
    float* __restrict__ out)         // [16, 3, 640, 640]
{
    __shared__ float s_buf[2][ROW_F];   // two vertically-summed rows
    __shared__ float s_sc[3], s_bi[3];

    const int t = threadIdx.x;
    if (t < 3) {
        const float inv = 1.0f / stdv[t];
        s_sc[t] = (0.5f / 255.0f) * inv;   // vertical 0.5 folded in
        s_bi[t] = -mean[t] * inv;
    }

    // prologue: stage row r into buffer 0
    int r = blockIdx.x;
    {
        const int b = r / OUT_HW, y = r - b * OUT_HW;
        const float4* __restrict__ s0 =
            (const float4*)(img + (size_t)(b * IN_H + 2 * y) * ROW_F);
        const float4* __restrict__ s1 = s0 + ROW_F4;
        float4* d4 = (float4*)s_buf[0];
#pragma unroll
        for (int j = 0; j < 3; ++j) {
            const int idx = t + j * NT;
            const float4 a = __ldg(&s0[idx]);
            const float4 c = __ldg(&s1[idx]);
            float4 m;
            m.x = a.x + c.x;  m.y = a.y + c.y;
            m.z = a.z + c.z;  m.w = a.w + c.w;
            d4[idx] = m;
        }
    }
    __syncthreads();

    int k = 0;
#pragma unroll 1
    for (int i = 0; i < ITERS; ++i, k ^= 1) {
        // (1) prefetch next row-pair into registers
        float4 n0[3], n1[3];
        const int rn = r + NBLK;
        if (i < ITERS - 1) {
            const int bn = rn / OUT_HW, yn = rn - bn * OUT_HW;
            const float4* __restrict__ s0 =
                (const float4*)(img + (size_t)(bn * IN_H + 2 * yn) * ROW_F);
            const float4* __restrict__ s1 = s0 + ROW_F4;
#pragma unroll
            for (int j = 0; j < 3; ++j) {
                n0[j] = __ldg(&s0[t + j * NT]);
                n1[j] = __ldg(&s1[t + j * NT]);
            }
        }

        // (2) compute current row from buffer k
        if (t < 160) {
            const int b = r / OUT_HW, y = r - b * OUT_HW;
            float v[18];
            const float2* sp = (const float2*)&s_buf[k][18 * t];  // 8B aligned
#pragma unroll
            for (int j = 0; j < 9; ++j) {
                const float2 p = sp[j];
                v[2 * j]     = p.x;
                v[2 * j + 1] = p.y;
            }
            const int ob = b * 3 * PLANE + y * OUT_HW + 4 * t;
#pragma unroll
            for (int c = 0; c < 3; ++c) {
                const float a0 = v[c],      a1 = v[3 + c],  a2 = v[6 + c];
                const float a3 = v[9 + c],  a4 = v[12 + c], a5 = v[15 + c];
                float4 o;
                o.x = fmaf(a1 - a0, 0.25f, a0);   // x = 4t   (fx=.25)
                o.y = fmaf(a2 - a1, 0.75f, a1);   // x = 4t+1 (fx=.75)
                o.z = fmaf(a4 - a3, 0.25f, a3);   // x = 4t+2
                o.w = fmaf(a5 - a4, 0.75f, a4);   // x = 4t+3
                const float sc = s_sc[c], bi = s_bi[c];
                o.x = fmaf(o.x, sc, bi);
                o.y = fmaf(o.y, sc, bi);
                o.z = fmaf(o.z, sc, bi);
                o.w = fmaf(o.w, sc, bi);
                __stcs((float4*)&out[ob + c * PLANE], o);
            }
        }

        // (3) stage prefetched pair into buffer k^1
        if (i < ITERS - 1) {
            float4* d4 = (float4*)s_buf[k ^ 1];
#pragma unroll
            for (int j = 0; j < 3; ++j) {
                float4 m;
                m.x = n0[j].x + n1[j].x;  m.y = n0[j].y + n1[j].y;
                m.z = n0[j].z + n1[j].z;  m.w = n0[j].w + n1[j].w;
                d4[t + j * NT] = m;
            }
        }

        // (4) single barrier between iterations
        __syncthreads();
        r = rn;
    }
}

extern "C" void kernel_launch(void* const* d_in, const int* in_sizes, int n_in,
                              void* d_out, int out_size) {
    const float* img  = (const float*)d_in[0];
    const float* mean = (const float*)d_in[1];
    const float* stdv = (const float*)d_in[2];
    float* out = (float*)d_out;

    preproc_pipe_kernel<<<NBLK, NT>>>(img, mean, stdv, out);
}

// round 10
// speedup vs baseline: 1.0303x; 1.0303x over previous
#include <cuda_runtime.h>
#include <cuda_bf16.h>

// Fused preprocessing: rescale(1/255) -> bilinear 1280x960 -> 640x640
// (half-pixel centers) -> normalize -> NHWC->NCHW.
//
// Micro-tuned version of the best (R2) kernel:
//  * 2 output rows per block, NT=320: the compute phase uses exactly all
//    320 threads (2 rows x 160), eliminating R2's 2.5 idle warps/block.
//  * __ldcs on input (read-once) and __stcs on output (write-once): keep
//    both streams out of L2 residency.
//  * Same winning shape otherwise: stage vertically-SUMMED rows (exact 0.5
//    vertical weight folded into normalize scale) -> 23KB smem, ONE barrier,
//    low register count; __launch_bounds__(320,6) targets 60 warps/SM.
// Horizontal 1.5 scale: px group {4t..4t+3} uses input cols {6t..6t+5},
// fracs {.25,.75,.25,.75}. No clamping needed at these shapes.

#define IN_H    1280
#define IN_W    960
#define OUT_HW  640
#define ROW_F   (IN_W * 3)       // 2880 floats per input row
#define ROW_F4  (ROW_F / 4)      // 720 float4
#define NT      320
#define PLANE   (OUT_HW * OUT_HW)
#define NBLK    (16 * OUT_HW / 2)   // 5120 blocks, 2 output rows each

__global__ __launch_bounds__(NT, 6) void preproc_kernel(
    const float* __restrict__ img,   // [16, 1280, 960, 3]
    const float* __restrict__ mean,  // [3]
    const float* __restrict__ stdv,  // [3]
    float* __restrict__ out)         // [16, 3, 640, 640]
{
    __shared__ float s_buf[2][ROW_F];   // two vertically-summed rows, 23 KB
    __shared__ float s_sc[3], s_bi[3];

    const int t = threadIdx.x;
    if (t < 3) {
        const float inv = 1.0f / stdv[t];
        s_sc[t] = (0.5f / 255.0f) * inv;   // vertical 0.5 folded in
        s_bi[t] = -mean[t] * inv;
    }

    const int u  = blockIdx.x;        // 0..5119
    const int b  = u >> 8 >> 1 >> 0;  // placeholder removed below
    // u -> (batch, row-pair): 320 row-pairs per batch
    const int bb = u / 320;           // batch 0..15
    const int yy = u - bb * 320;      // row-pair 0..319 (output rows 2yy,2yy+1)
    (void)b;

    // ---- stage: 1440 summed float4 (2 rows x 720) from 2880 input float4 ----
    // averaged element e in [0,1440): row = e/720, col = e%720
    //   input: rows (4yy + 2*row, 4yy + 2*row + 1)
    const float4* __restrict__ base4 =
        (const float4*)(img + (size_t)(bb * IN_H + 4 * yy) * ROW_F);
    float4* s4 = (float4*)s_buf[0];   // [2][720] flat = 1440
#pragma unroll
    for (int j = 0; j < 5; ++j) {
        const int e = t + j * NT;     // j<4 always valid; j==4 only t<160
        if (j < 4 || t < 160) {
            const int row = e / ROW_F4;
            const int col = e - row * ROW_F4;
            const float4* p0 = base4 + (size_t)(2 * row) * ROW_F4 + col;
            const float4 a = __ldcs(p0);
            const float4 c = __ldcs(p0 + ROW_F4);
            float4 m;
            m.x = a.x + c.x;  m.y = a.y + c.y;
            m.z = a.z + c.z;  m.w = a.w + c.w;
            s4[e] = m;
        }
    }
    __syncthreads();

    // ---- compute: all 320 threads; thread -> (row ri, px-group tt) ----
    const int ri = t / 160;           // 0 or 1
    const int tt = t - ri * 160;      // 0..159 -> px {4tt..4tt+3}
    float v[18];
    const float2* sp = (const float2*)&s_buf[ri][18 * tt];   // 8B aligned
#pragma unroll
    for (int j = 0; j < 9; ++j) {
        const float2 p = sp[j];
        v[2 * j]     = p.x;
        v[2 * j + 1] = p.y;
    }

    const int y  = 2 * yy + ri;
    const int ob = bb * 3 * PLANE + y * OUT_HW + 4 * tt;
#pragma unroll
    for (int c = 0; c < 3; ++c) {
        const float a0 = v[c],      a1 = v[3 + c],  a2 = v[6 + c];
        const float a3 = v[9 + c],  a4 = v[12 + c], a5 = v[15 + c];
        float4 o;
        o.x = fmaf(a1 - a0, 0.25f, a0);   // x = 4tt   (fx=.25)
        o.y = fmaf(a2 - a1, 0.75f, a1);   // x = 4tt+1 (fx=.75)
        o.z = fmaf(a4 - a3, 0.25f, a3);   // x = 4tt+2
        o.w = fmaf(a5 - a4, 0.75f, a4);   // x = 4tt+3
        const float sc = s_sc[c], bi = s_bi[c];
        o.x = fmaf(o.x, sc, bi);
        o.y = fmaf(o.y, sc, bi);
        o.z = fmaf(o.z, sc, bi);
        o.w = fmaf(o.w, sc, bi);
        __stcs((float4*)&out[ob + c * PLANE], o);
    }
}

extern "C" void kernel_launch(void* const* d_in, const int* in_sizes, int n_in,
                              void* d_out, int out_size) {
    const float* img  = (const float*)d_in[0];
    const float* mean = (const float*)d_in[1];
    const float* stdv = (const float*)d_in[2];
    float* out = (float*)d_out;

    preproc_kernel<<<NBLK, NT>>>(img, mean, stdv, out);
}

// round 11
// speedup vs baseline: 1.0419x; 1.0113x over previous
#include <cuda_runtime.h>
#include <cuda_bf16.h>

// Fused preprocessing: rescale(1/255) -> bilinear 1280x960 -> 640x640
// (half-pixel centers) -> normalize -> NHWC->NCHW.
//
// This is the best-measured (R2) kernel shape, unchanged, with EXACTLY ONE
// modification: staging loads use __ldcs (evict-first). The input stream is
// read-once (236 MB sweeping the 126 MB L2 ~2x), so evict-first preserves L2
// capacity for the output write-back stream.
//
// Structure: vertical scale is exactly 2.0 (frac always 0.5), so each output
// row is the average of input rows 2y and 2y+1 (0.5 folded into the staging
// multiply). One block per (output row, batch):
//   stage: float4-coalesced loads of both input rows, averaged in registers,
//          ONE averaged row (2880 floats) written to smem.
//   compute: each of 160 threads produces 4 consecutive output px from 18
//          contiguous smem floats, applies folded rescale+normalize FMA, and
//          writes one float4 per channel plane (coalesced STG.128).
// Horizontal: src_x = 1.5x + 0.25 -> px group {4t..4t+3} uses input cols
// {6t..6t+5} with fracs {.25,.75,.25,.75}. No clamping needed at these shapes.

#define IN_H    1280
#define IN_W    960
#define OUT_HW  640
#define ROW_F   (IN_W * 3)     // 2880 floats per input row
#define ROW_F4  (ROW_F / 4)    // 720 float4
#define NT      240            // 720 float4 / 240 = 3 staging iters
#define PLANE   (OUT_HW * OUT_HW)

__global__ __launch_bounds__(NT) void preproc_kernel(
    const float* __restrict__ img,   // [16, 1280, 960, 3]
    const float* __restrict__ mean,  // [3]
    const float* __restrict__ stdv,  // [3]
    float* __restrict__ out)         // [16, 3, 640, 640]
{
    __shared__ float s_row[ROW_F];      // vertically averaged input row
    __shared__ float s_scale[3];
    __shared__ float s_bias[3];

    const int t = threadIdx.x;
    if (t < 3) {
        const float inv = 1.0f / stdv[t];
        s_scale[t] = (1.0f / 255.0f) * inv;
        s_bias[t]  = -mean[t] * inv;
    }

    const int y = blockIdx.x;   // 0..639
    const int b = blockIdx.y;   // 0..15

    // ---- stage: rows 2y, 2y+1 -> averaged row in smem (float4 coalesced) ----
    const float4* __restrict__ r0 =
        (const float4*)(img + (size_t)(b * IN_H + 2 * y) * ROW_F);
    const float4* __restrict__ r1 = r0 + ROW_F4;
    float4* s4 = (float4*)s_row;
#pragma unroll
    for (int j = 0; j < 3; ++j) {
        const int idx = t + j * NT;
        float4 a = __ldcs(&r0[idx]);    // evict-first: read-once stream
        float4 c = __ldcs(&r1[idx]);
        float4 m;
        m.x = 0.5f * (a.x + c.x);
        m.y = 0.5f * (a.y + c.y);
        m.z = 0.5f * (a.z + c.z);
        m.w = 0.5f * (a.w + c.w);
        s4[idx] = m;
    }
    __syncthreads();

    // ---- compute: 4 output px per thread, threads 0..159 ----
    if (t < 160) {
        float v[18];
        const float2* sp = (const float2*)&s_row[18 * t];  // 8B-aligned (t*72B)
#pragma unroll
        for (int j = 0; j < 9; ++j) {
            float2 p = sp[j];
            v[2 * j]     = p.x;
            v[2 * j + 1] = p.y;
        }

        const int ob = b * 3 * PLANE + y * OUT_HW + 4 * t;
#pragma unroll
        for (int c = 0; c < 3; ++c) {
            const float a0 = v[c],      a1 = v[3 + c],  a2 = v[6 + c];
            const float a3 = v[9 + c],  a4 = v[12 + c], a5 = v[15 + c];
            float4 o;
            o.x = fmaf(a1 - a0, 0.25f, a0);   // x = 4t   (even, fx=.25)
            o.y = fmaf(a2 - a1, 0.75f, a1);   // x = 4t+1 (odd,  fx=.75)
            o.z = fmaf(a4 - a3, 0.25f, a3);   // x = 4t+2
            o.w = fmaf(a5 - a4, 0.75f, a4);   // x = 4t+3
            const float sc = s_scale[c], bi = s_bias[c];
            o.x = fmaf(o.x, sc, bi);
            o.y = fmaf(o.y, sc, bi);
            o.z = fmaf(o.z, sc, bi);
            o.w = fmaf(o.w, sc, bi);
            *(float4*)&out[ob + c * PLANE] = o;
        }
    }
}

extern "C" void kernel_launch(void* const* d_in, const int* in_sizes, int n_in,
                              void* d_out, int out_size) {
    const float* img  = (const float*)d_in[0];
    const float* mean = (const float*)d_in[1];
    const float* stdv = (const float*)d_in[2];
    float* out = (float*)d_out;

    dim3 block(NT, 1, 1);
    dim3 grid(OUT_HW, 16, 1);   // (640 rows, 16 batches)
    preproc_kernel<<<grid, block>>>(img, mean, stdv, out);
}